// round 2
// baseline (speedup 1.0000x reference)
#include <cuda_runtime.h>
#include <cstdint>

#define BTOT   65536
#define HDIM   128
#define KTOT   384
#define NG     512
#define MT     64
#define KC     32
#define NCHUNK 12
#define THREADS 256

#define AS_STRIDE 36
#define BS_STRIDE 520
#define AS_ELEMS (MT * AS_STRIDE)          // 2304 floats per buffer
#define BS_ELEMS (KC * BS_STRIDE)          // 16640 floats per buffer
#define SMEM_FLOATS (2 * AS_ELEMS + 2 * BS_ELEMS + KTOT)
#define SMEM_BYTES  (SMEM_FLOATS * 4)

// Scratch: packed weight matrix [W;R;U] (gate cols, tf32-rounded) and z-column (fp32)
__device__ float g_Bpack[KTOT * NG];
__device__ float g_Wz[KTOT];

__device__ __forceinline__ uint32_t f2tf32(float x) {
    uint32_t r;
    asm("cvt.rna.tf32.f32 %0, %1;" : "=r"(r) : "f"(x));
    return r;
}
__device__ __forceinline__ void cp16(uint32_t dst, const void* src) {
    asm volatile("cp.async.ca.shared.global [%0], [%1], 16;" :: "r"(dst), "l"(src));
}
__device__ __forceinline__ void cp_commit() { asm volatile("cp.async.commit_group;"); }
__device__ __forceinline__ void cp_wait0()  { asm volatile("cp.async.wait_group 0;"); }

__device__ __forceinline__ float sigm(float x) { return 1.f / (1.f + __expf(-x)); }
__device__ __forceinline__ float tanhfast(float x) { return 1.f - 2.f / (__expf(2.f * x) + 1.f); }

__device__ __forceinline__ void mma_tf32(float* d, const uint32_t* a, const uint32_t* b) {
    asm volatile(
        "mma.sync.aligned.m16n8k8.row.col.f32.tf32.tf32.f32 "
        "{%0,%1,%2,%3}, {%4,%5,%6,%7}, {%8,%9}, {%0,%1,%2,%3};"
        : "+f"(d[0]), "+f"(d[1]), "+f"(d[2]), "+f"(d[3])
        : "r"(a[0]), "r"(a[1]), "r"(a[2]), "r"(a[3]), "r"(b[0]), "r"(b[1]));
}

// ---------------------------------------------------------------------------
// Pack kernel: build [W;R;U] gate columns (tf32-rounded fp32) + fp32 z-column.
// ---------------------------------------------------------------------------
__global__ void pack_kernel(const float* __restrict__ W, const float* __restrict__ R,
                            const float* __restrict__ U) {
    int idx = blockIdx.x * blockDim.x + threadIdx.x;
    if (idx >= KTOT * 513) return;
    int kk = idx / 513;
    int n  = idx - kk * 513;
    float v;
    if (kk < 128)      v = W[kk * 513 + n];
    else if (kk < 256) v = R[(kk - 128) * 513 + n];
    else               v = U[(kk - 256) * 513 + n];
    if (n < NG) g_Bpack[kk * NG + n] = __uint_as_float(f2tf32(v));
    else        g_Wz[kk] = v;   // z column stays full fp32
}

// ---------------------------------------------------------------------------
// Fused HMLSTM kernel: TF32 GEMM (gates) + fp32 z-dot + gated epilogue.
// CTA: 256 threads (8 warps), 64 rows. Warp w owns cols [w*16, w*16+16) in
// each of the 4 gate blocks, so i/g/o/f for a (row,j) live in one thread.
// ---------------------------------------------------------------------------
__global__ __launch_bounds__(THREADS, 1)
void hmlstm_kernel(const float* __restrict__ hb, const float* __restrict__ hmat,
                   const float* __restrict__ ht, const float* __restrict__ cmat,
                   const float* __restrict__ zv, const float* __restrict__ zbv,
                   const float* __restrict__ bias, float* __restrict__ out) {
    extern __shared__ float smem[];
    float* As  = smem;                               // [2][MT][AS_STRIDE]
    float* Bs  = smem + 2 * AS_ELEMS;                // [2][KC][BS_STRIDE]
    float* Wzs = smem + 2 * AS_ELEMS + 2 * BS_ELEMS; // [KTOT]

    const int tid  = threadIdx.x;
    const int wid  = tid >> 5;
    const int lane = tid & 31;
    const int gid  = lane >> 2;   // 0..7
    const int tig  = lane & 3;    // 0..3
    const int m0   = blockIdx.x * MT;

    const uint32_t s_base  = (uint32_t)__cvta_generic_to_shared(smem);
    const uint32_t bs_base = s_base + 2u * AS_ELEMS * 4u;

    for (int i = tid; i < KTOT; i += THREADS) Wzs[i] = g_Wz[i];

    float acc[4][4][2][4];
#pragma unroll
    for (int mi = 0; mi < 4; mi++)
#pragma unroll
        for (int g = 0; g < 4; g++)
#pragma unroll
            for (int ni = 0; ni < 2; ni++)
#pragma unroll
                for (int q = 0; q < 4; q++) acc[mi][g][ni][q] = 0.f;

    // A staging registers (LDG early, STS late to overlap with MMA)
    float4 av[2];
    float  asc[2];

    auto issueB = [&](int ch, int p) {
        const float* src = g_Bpack + (size_t)ch * KC * NG;
        uint32_t dst0 = bs_base + (uint32_t)p * BS_ELEMS * 4u;
#pragma unroll
        for (int it = 0; it < 16; ++it) {
            int i  = it * THREADS + tid;      // 0..4095
            int kr = i >> 7;                  // 0..31
            int nf = i & 127;                 // float4 index within row
            cp16(dst0 + (uint32_t)(kr * BS_STRIDE + nf * 4) * 4u,
                 src + kr * NG + nf * 4);
        }
    };
    auto ldgA = [&](int ch) {
        int srcid = ch >> 2;
        int ko    = (ch & 3) * KC;
        const float* x = (srcid == 0) ? hb : ((srcid == 1) ? hmat : ht);
#pragma unroll
        for (int it = 0; it < 2; ++it) {
            int i = it * THREADS + tid;       // 0..511
            int r = i >> 3, f = i & 7;
            av[it]  = *(const float4*)(x + (size_t)(m0 + r) * HDIM + ko + f * 4);
            asc[it] = (srcid == 0) ? zbv[m0 + r] : ((srcid == 2) ? zv[m0 + r] : 1.f);
        }
    };
    auto stsA = [&](int p) {
#pragma unroll
        for (int it = 0; it < 2; ++it) {
            int i = it * THREADS + tid;
            int r = i >> 3, f = i & 7;
            float4 v = av[it];
            float  s = asc[it];
            v.x *= s; v.y *= s; v.z *= s; v.w *= s;
            *(float4*)(As + p * AS_ELEMS + r * AS_STRIDE + f * 4) = v;
        }
    };

    // Prologue: chunk 0
    issueB(0, 0); cp_commit();
    ldgA(0); stsA(0);
    cp_wait0();
    __syncthreads();

    float zacc = 0.f;
    const int zr = tid >> 2;        // local row for z-dot (0..63)
    const int zk = (tid & 3) * 8;   // k sub-range

    for (int ch = 0; ch < NCHUNK; ++ch) {
        int p = ch & 1;
        if (ch + 1 < NCHUNK) {
            issueB(ch + 1, p ^ 1); cp_commit();
            ldgA(ch + 1);
        }
        const float* Ap = As + p * AS_ELEMS;
        const float* Bp = Bs + p * BS_ELEMS;

#pragma unroll
        for (int ks = 0; ks < 4; ++ks) {
            uint32_t af[4][4];
#pragma unroll
            for (int mi = 0; mi < 4; mi++) {
                const float* a = Ap + (mi * 16 + gid) * AS_STRIDE + ks * 8 + tig;
                af[mi][0] = f2tf32(a[0]);
                af[mi][1] = f2tf32(a[8 * AS_STRIDE]);
                af[mi][2] = f2tf32(a[4]);
                af[mi][3] = f2tf32(a[8 * AS_STRIDE + 4]);
            }
            uint32_t bf[4][2][2];
#pragma unroll
            for (int g = 0; g < 4; g++)
#pragma unroll
                for (int ni = 0; ni < 2; ni++) {
                    int n = g * 128 + wid * 16 + ni * 8 + gid;
                    bf[g][ni][0] = __float_as_uint(Bp[(ks * 8 + tig) * BS_STRIDE + n]);
                    bf[g][ni][1] = __float_as_uint(Bp[(ks * 8 + tig + 4) * BS_STRIDE + n]);
                }
#pragma unroll
            for (int mi = 0; mi < 4; mi++)
#pragma unroll
                for (int g = 0; g < 4; g++)
#pragma unroll
                    for (int ni = 0; ni < 2; ni++)
                        mma_tf32(acc[mi][g][ni], af[mi], bf[g][ni]);
        }

        // fp32 z-column partial dot (reads unrounded, scaled A from smem)
#pragma unroll
        for (int kk = 0; kk < 8; kk++)
            zacc += Ap[zr * AS_STRIDE + zk + kk] * Wzs[ch * KC + zk + kk];

        if (ch + 1 < NCHUNK) { stsA(p ^ 1); cp_wait0(); }
        __syncthreads();
    }

    // z_new: reduce 4 partials per row, hard threshold (sz > 0)
    zacc += __shfl_xor_sync(0xffffffffu, zacc, 1);
    zacc += __shfl_xor_sync(0xffffffffu, zacc, 2);
    if ((tid & 3) == 0) {
        int gr = m0 + zr;
        float sz = zacc + __ldg(bias + 512);
        out[(size_t)BTOT * 256 + gr] = (sz > 0.f) ? 1.f : 0.f;
    }

    // Epilogue: gates -> h_new, c_new (register-local, no smem staging)
    float* outH = out;
    float* outC = out + (size_t)BTOT * HDIM;
#pragma unroll
    for (int mi = 0; mi < 4; mi++) {
#pragma unroll
        for (int half = 0; half < 2; ++half) {
            int rl = mi * 16 + gid + half * 8;
            int gr = m0 + rl;
            float zr_ = zv[gr];
            float zbr = zbv[gr];
            bool flush  = (zr_ == 1.f);
            bool copyc  = (zbr == 0.f);
            bool keep_h = (zr_ == 0.f) && (zbr == 0.f);
#pragma unroll
            for (int ni = 0; ni < 2; ni++) {
                int j = wid * 16 + ni * 8 + tig * 2;
                float2 cc = *(const float2*)(cmat + (size_t)gr * HDIM + j);
                float2 hh = *(const float2*)(hmat + (size_t)gr * HDIM + j);
                float hn2[2], cn2[2];
#pragma unroll
                for (int q = 0; q < 2; q++) {
                    int reg = half * 2 + q;
                    float si = acc[mi][0][ni][reg] + __ldg(bias + j + q);
                    float sg = acc[mi][1][ni][reg] + __ldg(bias + 128 + j + q);
                    float so = acc[mi][2][ni][reg] + __ldg(bias + 256 + j + q);
                    float sf = acc[mi][3][ni][reg] + __ldg(bias + 384 + j + q);
                    float iv = sigm(si);
                    float gv = tanhfast(sg);
                    float ov = sigm(so);
                    float fv = sigm(sf);
                    float ig = iv * gv;
                    float cold = q ? cc.y : cc.x;
                    float cn = flush ? ig : (copyc ? cold : fmaf(cold, fv, ig));
                    float hn = keep_h ? (q ? hh.y : hh.x) : tanhfast(cn) * ov;
                    cn2[q] = cn;
                    hn2[q] = hn;
                }
                *(float2*)(outH + (size_t)gr * HDIM + j) = make_float2(hn2[0], hn2[1]);
                *(float2*)(outC + (size_t)gr * HDIM + j) = make_float2(cn2[0], cn2[1]);
            }
        }
    }
}

extern "C" void kernel_launch(void* const* d_in, const int* in_sizes, int n_in,
                              void* d_out, int out_size) {
    const float* hb = (const float*)d_in[0];
    const float* h  = (const float*)d_in[1];
    const float* ht = (const float*)d_in[2];
    const float* c  = (const float*)d_in[3];
    const float* z  = (const float*)d_in[4];
    const float* zb = (const float*)d_in[5];
    const float* W  = (const float*)d_in[6];
    const float* R  = (const float*)d_in[7];
    const float* U  = (const float*)d_in[8];
    const float* b  = (const float*)d_in[9];
    float* out = (float*)d_out;
    (void)in_sizes; (void)n_in; (void)out_size;

    pack_kernel<<<(KTOT * 513 + 255) / 256, 256>>>(W, R, U);

    cudaFuncSetAttribute(hmlstm_kernel,
                         cudaFuncAttributeMaxDynamicSharedMemorySize, SMEM_BYTES);
    hmlstm_kernel<<<BTOT / MT, THREADS, SMEM_BYTES>>>(hb, h, ht, c, z, zb, b, out);
}

// round 4
// speedup vs baseline: 1.1907x; 1.1907x over previous
#include <cuda_runtime.h>
#include <cstdint>

#define BTOT   65536
#define HDIM   128
#define KTOT   384
#define NG     512
#define MT     64
#define KC     32
#define NCHUNK 12
#define THREADS 512
#define NKI    (NCHUNK * 4)

// B pre-packed in per-warp fragment order: [ch][w16][ks4][g4][lane32][2]
__device__ float g_Bpk[NCHUNK * 16 * 16 * 64];
__device__ float g_Wz[KTOT];

__device__ __forceinline__ uint32_t f2tf32(float x) {
    uint32_t r;
    asm("cvt.rna.tf32.f32 %0, %1;" : "=r"(r) : "f"(x));
    return r;
}
__device__ __forceinline__ float sigm(float x)     { return 1.f / (1.f + __expf(-x)); }
__device__ __forceinline__ float tanhfast(float x) { return 1.f - 2.f / (__expf(2.f * x) + 1.f); }

__device__ __forceinline__ void mma_tf32(float* d, const uint32_t* a, const uint32_t* b) {
    asm volatile(
        "mma.sync.aligned.m16n8k8.row.col.f32.tf32.tf32.f32 "
        "{%0,%1,%2,%3}, {%4,%5,%6,%7}, {%8,%9}, {%0,%1,%2,%3};"
        : "+f"(d[0]), "+f"(d[1]), "+f"(d[2]), "+f"(d[3])
        : "r"(a[0]), "r"(a[1]), "r"(a[2]), "r"(a[3]), "r"(b[0]), "r"(b[1]));
}

// ---------------------------------------------------------------------------
// Pack: [W;R;U] -> fragment-ordered, tf32-rounded B + fp32 z-column
// ---------------------------------------------------------------------------
__global__ void pack_kernel(const float* __restrict__ W, const float* __restrict__ R,
                            const float* __restrict__ U) {
    int o = blockIdx.x * blockDim.x + threadIdx.x;
    const int NB = NCHUNK * 16 * 16 * 64;
    if (o < NB) {
        int l2   = o & 63;
        int lane = l2 >> 1, half = l2 & 1;
        int gid  = lane >> 2, tig = lane & 3;
        int t  = o >> 6;
        int g  = t & 3, ks = (t >> 2) & 3, w = (t >> 4) & 15, ch = t >> 8;
        int k  = ch * KC + ks * 8 + tig + half * 4;
        int n  = g * 128 + w * 8 + gid;
        const float* src = (k < 128) ? W : (k < 256) ? R : U;
        g_Bpk[o] = __uint_as_float(f2tf32(src[(k & 127) * 513 + n]));
    } else if (o - NB < KTOT) {
        int k = o - NB;
        const float* src = (k < 128) ? W : (k < 256) ? R : U;
        g_Wz[k] = src[(k & 127) * 513 + 512];
    }
}

// ---------------------------------------------------------------------------
// Fused HMLSTM: mma.sync tf32 GEMM + exact fp32 z-dot + gated epilogue
// 512 threads, 64-row tile, warp w owns 8 cols (w*8..w*8+7) in each gate block.
// ---------------------------------------------------------------------------
__global__ __launch_bounds__(THREADS, 1)
void hmlstm_kernel(const float* __restrict__ hb, const float* __restrict__ hm,
                   const float* __restrict__ ht, const float* __restrict__ cm,
                   const float* __restrict__ zv, const float* __restrict__ zbv,
                   const float* __restrict__ bias, float* __restrict__ out) {
    __shared__ float sA[2][2048];   // fragment-ready A, 8KB per stage

    const int tid  = threadIdx.x;
    const int w    = tid >> 5;
    const int lane = tid & 31;
    const int gid  = lane >> 2;
    const int tig  = lane & 3;
    const int m0   = blockIdx.x * MT;

    // loader indexing: thread -> (row lr, float4-slice lf)
    const int lr  = tid >> 3;          // 0..63
    const int lf  = tid & 7;           // 0..7
    const int lmi = lr >> 4, lgid = lr & 7, lrh = (lr >> 3) & 1;
    const int lks = lf >> 1, lkh = lf & 1;
    const int sbase = lmi * 512 + lks * 128 + lgid * 16 + lrh + 2 * lkh;

    float acc[4][4][4];
#pragma unroll
    for (int mi = 0; mi < 4; mi++)
#pragma unroll
        for (int g = 0; g < 4; g++)
#pragma unroll
            for (int q = 0; q < 4; q++) acc[mi][g][q] = 0.f;

    float4 av;
    float  zacc = 0.f;

    auto ldgA = [&](int ch) {
        int srcid = ch >> 2, ko = (ch & 3) * KC;
        const float* x = (srcid == 0) ? hb : (srcid == 1) ? hm : ht;
        float sc = (srcid == 0) ? __ldg(zbv + m0 + lr)
                 : (srcid == 2) ? __ldg(zv + m0 + lr) : 1.f;
        float4 v = __ldg((const float4*)(x + (size_t)(m0 + lr) * HDIM + ko + lf * 4));
        v.x *= sc; v.y *= sc; v.z *= sc; v.w *= sc;
        float4 wz = __ldg((const float4*)(g_Wz + ch * KC + lf * 4));
        zacc = fmaf(v.x, wz.x, fmaf(v.y, wz.y, fmaf(v.z, wz.z, fmaf(v.w, wz.w, zacc))));
        av = v;
    };
    auto stsA = [&](int s) {
        float* A = sA[s];
        float vv[4] = {av.x, av.y, av.z, av.w};
#pragma unroll
        for (int q = 0; q < 4; q++)
            A[sbase + ((q ^ lks) & 3) * 4] = __uint_as_float(f2tf32(vv[q]));
    };
    auto ldB = [&](int ki, float2* b) {
        const float2* p = (const float2*)g_Bpk +
            (size_t)((((ki >> 2) * 16 + w) * 16 + (ki & 3) * 4)) * 32 + lane;
#pragma unroll
        for (int g = 0; g < 4; g++) b[g] = __ldg(p + g * 32);
    };

    float2 bcur[4], bnxt[4];

    // prologue
    ldgA(0); stsA(0); ldB(0, bcur);
    __syncthreads();

    for (int ch = 0; ch < NCHUNK; ++ch) {
        int s = ch & 1;
        if (ch + 1 < NCHUNK) ldgA(ch + 1);
        const float* A = sA[s];
#pragma unroll
        for (int ks = 0; ks < 4; ++ks) {
            int ki = ch * 4 + ks;
            if (ki + 1 < NKI) ldB(ki + 1, bnxt);
#pragma unroll
            for (int mi = 0; mi < 4; ++mi) {
                float4 a = *(const float4*)(A + mi * 512 + ks * 128 + gid * 16 +
                                            ((tig ^ ks) & 3) * 4);
                const uint32_t* au = (const uint32_t*)&a;
#pragma unroll
                for (int g = 0; g < 4; ++g)
                    mma_tf32(acc[mi][g], au, (const uint32_t*)&bcur[g]);
            }
#pragma unroll
            for (int g = 0; g < 4; ++g) bcur[g] = bnxt[g];
        }
        if (ch + 1 < NCHUNK) stsA(s ^ 1);
        __syncthreads();
    }

    // ---- z_new: exact fp32 dot, threshold sz > 0 ----
    {
        float v = zacc;
        v += __shfl_xor_sync(0xffffffffu, v, 1);
        v += __shfl_xor_sync(0xffffffffu, v, 2);
        v += __shfl_xor_sync(0xffffffffu, v, 4);
        if (lf == 0)
            out[(size_t)BTOT * 2 * HDIM + m0 + lr] =
                (v + __ldg(bias + 512) > 0.f) ? 1.f : 0.f;
    }

    // ---- epilogue: gates -> h_new, c_new (sector-coalesced float2 I/O) ----
    const int j0 = w * 8 + tig * 2;
    float bi[2], bg[2], bo[2], bfv[2];
#pragma unroll
    for (int q = 0; q < 2; q++) {
        bi[q]  = __ldg(bias + j0 + q);
        bg[q]  = __ldg(bias + 128 + j0 + q);
        bo[q]  = __ldg(bias + 256 + j0 + q);
        bfv[q] = __ldg(bias + 384 + j0 + q);
    }
    float* outH = out;
    float* outC = out + (size_t)BTOT * HDIM;
#pragma unroll
    for (int mi = 0; mi < 4; ++mi) {
#pragma unroll
        for (int rh = 0; rh < 2; ++rh) {
            int r  = mi * 16 + gid + rh * 8;
            int gr = m0 + r;
            float zr_ = __ldg(zv + gr), zbr = __ldg(zbv + gr);
            bool flush = (zr_ == 1.f);
            bool copyc = (zbr == 0.f);
            bool keeph = (zr_ == 0.f) && (zbr == 0.f);
            float2 cc = __ldg((const float2*)(cm + (size_t)gr * HDIM + j0));
            float2 hh = __ldg((const float2*)(hm + (size_t)gr * HDIM + j0));
            float hn[2], cn[2];
#pragma unroll
            for (int q = 0; q < 2; ++q) {
                int reg = rh * 2 + q;
                float si = acc[mi][0][reg] + bi[q];
                float sg = acc[mi][1][reg] + bg[q];
                float so = acc[mi][2][reg] + bo[q];
                float sf = acc[mi][3][reg] + bfv[q];
                float iv = sigm(si), gv = tanhfast(sg), ov = sigm(so), fv = sigm(sf);
                float ig = iv * gv;
                float cold = q ? cc.y : cc.x;
                float cnv = flush ? ig : (copyc ? cold : fmaf(cold, fv, ig));
                float hnv = keeph ? (q ? hh.y : hh.x) : tanhfast(cnv) * ov;
                cn[q] = cnv; hn[q] = hnv;
            }
            *(float2*)(outH + (size_t)gr * HDIM + j0) = make_float2(hn[0], hn[1]);
            *(float2*)(outC + (size_t)gr * HDIM + j0) = make_float2(cn[0], cn[1]);
        }
    }
}

extern "C" void kernel_launch(void* const* d_in, const int* in_sizes, int n_in,
                              void* d_out, int out_size) {
    const float* hb = (const float*)d_in[0];
    const float* h  = (const float*)d_in[1];
    const float* ht = (const float*)d_in[2];
    const float* c  = (const float*)d_in[3];
    const float* z  = (const float*)d_in[4];
    const float* zb = (const float*)d_in[5];
    const float* W  = (const float*)d_in[6];
    const float* R  = (const float*)d_in[7];
    const float* U  = (const float*)d_in[8];
    const float* b  = (const float*)d_in[9];
    float* out = (float*)d_out;
    (void)in_sizes; (void)n_in; (void)out_size;

    int total = NCHUNK * 16 * 16 * 64 + KTOT;
    pack_kernel<<<(total + 255) / 256, 256>>>(W, R, U);
    hmlstm_kernel<<<BTOT / MT, THREADS>>>(hb, h, ht, c, z, zb, b, out);
}